// round 8
// baseline (speedup 1.0000x reference)
#include <cuda_runtime.h>

#define FULL 0xffffffffu
constexpr int NW = 8;    // warps per block
constexpr int SPW = 8;   // samples per warp

__device__ __forceinline__ float sigm(float x) { return 1.0f / (1.0f + __expf(-x)); }

__device__ __forceinline__ float wsum(float t) {
#pragma unroll
    for (int o = 16; o; o >>= 1) t += __shfl_xor_sync(FULL, t, o);
    return t;
}

#define FMA4(acc, vec, arr, base)                  \
    acc = fmaf((vec).x, (arr)[(base) + 0], acc);   \
    acc = fmaf((vec).y, (arr)[(base) + 1], acc);   \
    acc = fmaf((vec).z, (arr)[(base) + 2], acc);   \
    acc = fmaf((vec).w, (arr)[(base) + 3], acc);

#define FMA4V(acc, vec, wv)                        \
    acc = fmaf((vec).x, (wv).x, acc);              \
    acc = fmaf((vec).y, (wv).y, acc);              \
    acc = fmaf((vec).z, (wv).z, acc);              \
    acc = fmaf((vec).w, (wv).w, acc);

#define DOT6(acc, r4, r2, q4, q2)                  \
    acc = fmaf((r4).x, (q4).x, acc);               \
    acc = fmaf((r4).y, (q4).y, acc);               \
    acc = fmaf((r4).z, (q4).z, acc);               \
    acc = fmaf((r4).w, (q4).w, acc);               \
    acc = fmaf((r2).x, (q2).x, acc);               \
    acc = fmaf((r2).y, (q2).y, acc);

// ================= Kernel 1: adjacency =================
// act layout: FSP 0 (48), ANF 48 (192), AU 240 (224, stride 36), AV 464 (224)
constexpr int K1_ACT = 688;

__global__ __launch_bounds__(256, 2) void k_adj(
    const float* __restrict__ factors,
    const float* __restrict__ Wn,  const float* __restrict__ bn,
    const float* __restrict__ We1, const float* __restrict__ be1,
    const float* __restrict__ We2, const float* __restrict__ be2,
    float* __restrict__ out, int Btot)
{
    __shared__ __align__(16) float we2S[32];
    __shared__ __align__(16) float act[NW][K1_ACT];

    const int tid = threadIdx.x;
    if (tid < 32) we2S[tid] = We2[tid];
    __syncthreads();

    const int lane = tid & 31;
    const int w = tid >> 5;
    float* A = act[w];

    const int i1 = lane / 6, j1 = lane - i1 * 6;
    const int j2 = (lane < 4) ? lane + 2 : 2;

    // hoisted weights, coalesced direct from gmem
    float wnc[6];
#pragma unroll
    for (int f = 0; f < 6; f++) wnc[f] = Wn[f * 32 + lane];
    float wu[32], wv[32];
#pragma unroll
    for (int k = 0; k < 32; k++) {
        wu[k] = We1[k * 32 + lane];
        wv[k] = We1[(32 + k) * 32 + lane];
    }
    const float bnl = bn[lane], be1l = be1[lane], be2v = be2[0];

#pragma unroll 1
    for (int s = 0; s < SPW; s++) {
        const int b = (blockIdx.x * NW + w) * SPW + s;
        if (b < Btot) {
            const float* fb = factors + (size_t)b * 36;
            A[i1 * 8 + j1] = fb[lane];
            if (lane < 4) A[40 + j2] = fb[32 + lane];
            __syncwarp();

            // node encoder -> ANF
#pragma unroll
            for (int i = 0; i < 6; i++) {
                float4 f4 = *(const float4*)&A[i * 8];
                float2 f2 = *(const float2*)&A[i * 8 + 4];
                float acc = bnl;
                acc = fmaf(f4.x, wnc[0], acc); acc = fmaf(f4.y, wnc[1], acc);
                acc = fmaf(f4.z, wnc[2], acc); acc = fmaf(f4.w, wnc[3], acc);
                acc = fmaf(f2.x, wnc[4], acc); acc = fmaf(f2.y, wnc[5], acc);
                A[48 + i * 32 + lane] = acc;
            }
            __syncwarp();

            // u,v with register weights (broadcast activation reads only)
#pragma unroll
            for (int i = 0; i < 6; i++) {
                float ui = be1l, vi = 0.0f;
#pragma unroll
                for (int t = 0; t < 8; t++) {
                    float4 nv = *(const float4*)&A[48 + i * 32 + 4 * t];
                    FMA4(ui, nv, wu, 4 * t);
                    FMA4(vi, nv, wv, 4 * t);
                }
                A[240 + i * 36 + lane] = ui;
                A[464 + i * 36 + lane] = vi;
            }
            __syncwarp();

            // adjacency (lane = edge)
            {
                float acc1 = 0.0f, acc2 = 0.0f;
#pragma unroll
                for (int t = 0; t < 8; t++) {
                    float4 w2 = *(const float4*)&we2S[4 * t];
                    float4 a1 = *(const float4*)&A[240 + i1 * 36 + 4 * t];
                    float4 b1 = *(const float4*)&A[464 + j1 * 36 + 4 * t];
                    acc1 = fmaf(fmaxf(a1.x + b1.x, 0.0f), w2.x, acc1);
                    acc1 = fmaf(fmaxf(a1.y + b1.y, 0.0f), w2.y, acc1);
                    acc1 = fmaf(fmaxf(a1.z + b1.z, 0.0f), w2.z, acc1);
                    acc1 = fmaf(fmaxf(a1.w + b1.w, 0.0f), w2.w, acc1);
                    float4 a2 = *(const float4*)&A[240 + 5 * 36 + 4 * t];
                    float4 b2 = *(const float4*)&A[464 + j2 * 36 + 4 * t];
                    acc2 = fmaf(fmaxf(a2.x + b2.x, 0.0f), w2.x, acc2);
                    acc2 = fmaf(fmaxf(a2.y + b2.y, 0.0f), w2.y, acc2);
                    acc2 = fmaf(fmaxf(a2.z + b2.z, 0.0f), w2.z, acc2);
                    acc2 = fmaf(fmaxf(a2.w + b2.w, 0.0f), w2.w, acc2);
                }
                float a1v = (i1 == j1) ? 0.0f : sigm(acc1 + be2v);
                float a2v = (lane == 3) ? 0.0f : sigm(acc2 + be2v);
                out[(size_t)b * 36 + lane] = a1v;
                if (lane < 4) out[(size_t)b * 36 + 32 + lane] = a2v;
            }
            __syncwarp();
        }
    }
}

// ================= Kernel 2: dynamics -> pred =================
// act: FSP 0 (48), ADJ 48 (48), ASP 96 (48), ANF 144 (192), AU 336 (224)
constexpr int K2_ACT = 560;

__global__ __launch_bounds__(256, 3) void k_dyn(
    const float* __restrict__ factors,
    const float* __restrict__ Wd1, const float* __restrict__ bd1,
    const float* __restrict__ Wd2, const float* __restrict__ bd2,
    const float* __restrict__ Wd3, const float* __restrict__ bd3,
    float* __restrict__ out, int Btot)
{
    __shared__ __align__(16) float wd3F[6 * 36];
    __shared__ __align__(16) float act[NW][K2_ACT];

    const int tid = threadIdx.x;
    for (int idx = tid; idx < 192; idx += 256) {
        int k3 = idx / 6, f3 = idx - k3 * 6;
        wd3F[f3 * 36 + k3] = Wd3[idx];
    }
    __syncthreads();

    const int lane = tid & 31;
    const int w = tid >> 5;
    float* A = act[w];

    const int i1 = lane / 6, j1 = lane - i1 * 6;
    const int j2 = (lane < 4) ? lane + 2 : 2;

    float wd1c[6], wd2c[32];
#pragma unroll
    for (int i = 0; i < 6; i++) wd1c[i] = Wd1[i * 32 + lane];
#pragma unroll
    for (int k = 0; k < 32; k++) wd2c[k] = Wd2[k * 32 + lane];
    const float bd1l = bd1[lane], bd2l = bd2[lane];
    const float bd3l = bd3[j1], bd3l2 = bd3[j2];

    const float* adjG = out;  // written by k_adj
    const size_t predBase = (size_t)Btot * 36;

#pragma unroll 1
    for (int s = 0; s < SPW; s++) {
        const int b = (blockIdx.x * NW + w) * SPW + s;
        if (b < Btot) {
            const float* fb = factors + (size_t)b * 36;
            const float* ab = adjG + (size_t)b * 36;
            A[i1 * 8 + j1] = fb[lane];
            A[48 + i1 * 8 + j1] = ab[lane];
            if (lane < 4) {
                A[40 + j2] = fb[32 + lane];
                A[48 + 40 + j2] = ab[32 + lane];
            }
            __syncwarp();

            // structured (lane = (n=i1, i=j1))
            {
                float4 ra4 = *(const float4*)&A[48 + j1 * 8];
                float2 ra2 = *(const float2*)&A[48 + j1 * 8 + 4];
                float4 rf4 = *(const float4*)&A[i1 * 8];
                float2 rf2 = *(const float2*)&A[i1 * 8 + 4];
                float sv = 0.0f;
                DOT6(sv, ra4, ra2, rf4, rf2);
                A[96 + i1 * 8 + j1] = sv;
                if (lane < 4) {
                    float4 qa4 = *(const float4*)&A[48 + j2 * 8];
                    float2 qa2 = *(const float2*)&A[48 + j2 * 8 + 4];
                    float4 qf4 = *(const float4*)&A[40];
                    float2 qf2 = *(const float2*)&A[44];
                    float sv2 = 0.0f;
                    DOT6(sv2, qa4, qa2, qf4, qf2);
                    A[96 + 40 + j2] = sv2;
                }
            }
            __syncwarp();

            // h1 (lane = hidden)
#pragma unroll
            for (int n = 0; n < 6; n++) {
                float4 s4 = *(const float4*)&A[96 + n * 8];
                float2 s2 = *(const float2*)&A[96 + n * 8 + 4];
                float acc = bd1l;
                acc = fmaf(s4.x, wd1c[0], acc); acc = fmaf(s4.y, wd1c[1], acc);
                acc = fmaf(s4.z, wd1c[2], acc); acc = fmaf(s4.w, wd1c[3], acc);
                acc = fmaf(s2.x, wd1c[4], acc); acc = fmaf(s2.y, wd1c[5], acc);
                A[144 + n * 32 + lane] = fmaxf(acc, 0.0f);
            }
            __syncwarp();

            // h2 (lane = hidden, register weights)
#pragma unroll
            for (int n = 0; n < 6; n++) {
                float acc = bd2l;
#pragma unroll
                for (int t = 0; t < 8; t++) {
                    float4 hv = *(const float4*)&A[144 + n * 32 + 4 * t];
                    FMA4(acc, hv, wd2c, 4 * t);
                }
                A[336 + n * 36 + lane] = fmaxf(acc, 0.0f);
            }
            __syncwarp();

            // pred (lane = (n=i1, f=j1)); wd3 via conflict-free smem broadcasts
            {
                float acc1 = 0.0f, acc2 = 0.0f;
#pragma unroll
                for (int t = 0; t < 8; t++) {
                    float4 hv = *(const float4*)&A[336 + i1 * 36 + 4 * t];
                    float4 w3a = *(const float4*)&wd3F[j1 * 36 + 4 * t];
                    FMA4V(acc1, hv, w3a);
                    float4 h5 = *(const float4*)&A[336 + 5 * 36 + 4 * t];
                    float4 w3b = *(const float4*)&wd3F[j2 * 36 + 4 * t];
                    FMA4V(acc2, h5, w3b);
                }
                float* op = out + predBase + (size_t)b * 36;
                op[lane] = acc1 + bd3l;
                if (lane < 4) op[32 + lane] = acc2 + bd3l2;
            }
            __syncwarp();
        }
    }
}

// ================= Kernel 3: anomaly scores =================
// act: FSP 0 (48), PSP 48 (48), ANF 96 (192)
constexpr int K3_ACT = 288;

__global__ __launch_bounds__(256, 3) void k_score(
    const float* __restrict__ factors,
    const float* __restrict__ Ws1, const float* __restrict__ bs1,
    const float* __restrict__ Ws2, const float* __restrict__ bs2,
    const float* __restrict__ Ws3, const float* __restrict__ bs3,
    float* __restrict__ out, int Btot)
{
    __shared__ __align__(16) float act[NW][K3_ACT];

    const int tid = threadIdx.x;
    const int lane = tid & 31;
    const int w = tid >> 5;
    float* A = act[w];

    const int i1 = lane / 6, j1 = lane - i1 * 6;
    const int j2 = (lane < 4) ? lane + 2 : 2;

    float ws1c[18], ws2c[32];
#pragma unroll
    for (int k = 0; k < 18; k++) ws1c[k] = Ws1[k * 32 + lane];
#pragma unroll
    for (int k = 0; k < 32; k++) ws2c[k] = Ws2[k * 16 + (lane & 15)];
    const float bs1l = bs1[lane];
    const float bs2l = bs2[lane & 15];
    const float ws3l = (lane < 16) ? Ws3[lane] : 0.0f;
    const float bs3v = bs3[0];

    const float* predG = out + (size_t)Btot * 36;
    const size_t scoreBase = (size_t)Btot * 72;

#pragma unroll 1
    for (int s = 0; s < SPW; s++) {
        const int b = (blockIdx.x * NW + w) * SPW + s;
        if (b < Btot) {
            const float* fb = factors + (size_t)b * 36;
            const float* pb = predG + (size_t)b * 36;
            A[i1 * 8 + j1] = fb[lane];
            A[48 + i1 * 8 + j1] = pb[lane];
            if (lane < 4) {
                A[40 + j2] = fb[32 + lane];
                A[48 + 40 + j2] = pb[32 + lane];
            }
            __syncwarp();

            // scorer layer 1 (lane = hidden)
#pragma unroll
            for (int n = 0; n < 6; n++) {
                float4 f4 = *(const float4*)&A[n * 8];
                float2 f2 = *(const float2*)&A[n * 8 + 4];
                float4 p4 = *(const float4*)&A[48 + n * 8];
                float2 p2 = *(const float2*)&A[48 + n * 8 + 4];
                float fk[6] = {f4.x, f4.y, f4.z, f4.w, f2.x, f2.y};
                float pk[6] = {p4.x, p4.y, p4.z, p4.w, p2.x, p2.y};
                float acc = bs1l;
#pragma unroll
                for (int k = 0; k < 6; k++) {
                    acc = fmaf(fk[k], ws1c[k], acc);
                    acc = fmaf(pk[k], ws1c[6 + k], acc);
                    acc = fmaf(fabsf(fk[k] - pk[k]), ws1c[12 + k], acc);
                }
                A[96 + n * 32 + lane] = fmaxf(acc, 0.0f);
            }
            __syncwarp();

            // scorer layers 2+3
            float ssum = 0.0f;
#pragma unroll
            for (int n = 0; n < 6; n++) {
                float acc = bs2l;
#pragma unroll
                for (int t = 0; t < 8; t++) {
                    float4 sv = *(const float4*)&A[96 + n * 32 + 4 * t];
                    FMA4(acc, sv, ws2c, 4 * t);
                }
                float tt = fmaxf(acc, 0.0f) * ws3l;  // lanes >= 16 contribute 0
                ssum += sigm(wsum(tt) + bs3v);
            }
            if (lane == 0) out[scoreBase + b] = ssum * (1.0f / 6.0f);
            __syncwarp();
        }
    }
}

extern "C" void kernel_launch(void* const* d_in, const int* in_sizes, int n_in,
                              void* d_out, int out_size) {
    const float* p[19];
    for (int i = 0; i < 19; i++) p[i] = (const float*)d_in[i];
    int Btot = in_sizes[0] / 36;
    int per_block = NW * SPW;
    int blocks = (Btot + per_block - 1) / per_block;
    float* out = (float*)d_out;

    k_adj<<<blocks, 256>>>(p[0], p[1], p[2], p[3], p[4], p[5], p[6], out, Btot);
    k_dyn<<<blocks, 256>>>(p[0], p[7], p[8], p[9], p[10], p[11], p[12], out, Btot);
    k_score<<<blocks, 256>>>(p[0], p[13], p[14], p[15], p[16], p[17], p[18], out, Btot);
}

// round 9
// speedup vs baseline: 1.2221x; 1.2221x over previous
#include <cuda_runtime.h>

#define FULL 0xffffffffu
constexpr int NW = 8;    // warps per block
constexpr int SPW = 8;   // samples per warp

// per-warp activation region offsets (floats); all 16B-aligned
constexpr int FSP = 0;    // factors, 6 rows stride 8 (48)
constexpr int ANF = 48;   // h1 / s1, i*32+lane (192)
constexpr int AU  = 240;  // u / h2, 6 rows stride 36
constexpr int AV  = 464;  // v, 6 rows stride 36
constexpr int ADJ = 680;  // adjacency, rows stride 8 (48)
constexpr int ASP = 728;  // structured / pred, rows stride 8 (48)
constexpr int ACT = 784;

__device__ __forceinline__ float sigm(float x) { return 1.0f / (1.0f + __expf(-x)); }

__device__ __forceinline__ float wsum(float t) {
#pragma unroll
    for (int o = 16; o; o >>= 1) t += __shfl_xor_sync(FULL, t, o);
    return t;
}

#define FMA4V(acc, vec, wv)                        \
    acc = fmaf((vec).x, (wv).x, acc);              \
    acc = fmaf((vec).y, (wv).y, acc);              \
    acc = fmaf((vec).z, (wv).z, acc);              \
    acc = fmaf((vec).w, (wv).w, acc);

#define LD4(arr, dst, off)                                        \
    { float4 _a = *(const float4*)&(arr)[off];                    \
      (dst)[0] = _a.x; (dst)[1] = _a.y; (dst)[2] = _a.z; (dst)[3] = _a.w; }

// dot6: row (float4,float2) against 6 scalar weights
#define DOT6S(acc, r4, r2, wc)                     \
    acc = fmaf((r4).x, (wc)[0], acc);              \
    acc = fmaf((r4).y, (wc)[1], acc);              \
    acc = fmaf((r4).z, (wc)[2], acc);              \
    acc = fmaf((r4).w, (wc)[3], acc);              \
    acc = fmaf((r2).x, (wc)[4], acc);              \
    acc = fmaf((r2).y, (wc)[5], acc);

#define DOT6(acc, r4, r2, q4, q2)                  \
    acc = fmaf((r4).x, (q4).x, acc);               \
    acc = fmaf((r4).y, (q4).y, acc);               \
    acc = fmaf((r4).z, (q4).z, acc);               \
    acc = fmaf((r4).w, (q4).w, acc);               \
    acc = fmaf((r2).x, (q2).x, acc);               \
    acc = fmaf((r2).y, (q2).y, acc);

__global__ __launch_bounds__(NW * 32, 3) void cad_kernel(
    const float* __restrict__ factors,
    const float* __restrict__ Wn,  const float* __restrict__ bn,
    const float* __restrict__ We1, const float* __restrict__ be1,
    const float* __restrict__ We2, const float* __restrict__ be2,
    const float* __restrict__ Wd1, const float* __restrict__ bd1,
    const float* __restrict__ Wd2, const float* __restrict__ bd2,
    const float* __restrict__ Wd3, const float* __restrict__ bd3,
    const float* __restrict__ Ws1, const float* __restrict__ bs1,
    const float* __restrict__ Ws2, const float* __restrict__ bs2,
    const float* __restrict__ Ws3, const float* __restrict__ bs3,
    float* __restrict__ out, int Btot)
{
    // composed edge-layer weights: Wu = Wn@We1[:32], Wv = Wn@We1[32:]
    __shared__ __align__(16) float WuS[192], WvS[192];
    __shared__ __align__(16) float buS[32], bvS[32];
    __shared__ __align__(16) float wd2T[32 * 36];
    __shared__ __align__(16) float wd3F[6 * 36];
    __shared__ __align__(16) float ws1T[32 * 20];
    __shared__ __align__(16) float ws2T[16 * 36];
    __shared__ __align__(16) float we2S[32];
    __shared__ float bd1S[32], bd2S[32], bs1S[32];
    __shared__ float bs2S[16], ws3S[16], bd3S[8], scal[2];
    __shared__ __align__(16) float act[NW][ACT];

    const int tid = threadIdx.x;

    // ---- composition: Wu[f][h] = sum_k Wn[f][k]*We1[k][h]; Wv with We1[32+k] ----
    if (tid < 192) {
        int f = tid >> 5, h = tid & 31;
        float au = 0.0f, av = 0.0f;
#pragma unroll 4
        for (int k = 0; k < 32; k++) {
            float wn = Wn[f * 32 + k];
            au = fmaf(wn, We1[k * 32 + h], au);
            av = fmaf(wn, We1[(32 + k) * 32 + h], av);
        }
        WuS[f * 32 + h] = au;
        WvS[f * 32 + h] = av;
    }
    if (tid < 32) {
        float bu = be1[tid], bv = 0.0f;
#pragma unroll 4
        for (int k = 0; k < 32; k++) {
            float b = bn[k];
            bu = fmaf(b, We1[k * 32 + tid], bu);
            bv = fmaf(b, We1[(32 + k) * 32 + tid], bv);
        }
        buS[tid] = bu; bvS[tid] = bv;
    }
    // ---- other weight staging / transposes ----
    for (int idx = tid; idx < 1024; idx += NW * 32) {
        int k = idx >> 5, l = idx & 31;
        wd2T[l * 36 + k] = Wd2[idx];
    }
    for (int idx = tid; idx < 576; idx += NW * 32) {
        int k = idx >> 5, l = idx & 31;
        ws1T[l * 20 + k] = Ws1[idx];
    }
    for (int idx = tid; idx < 512; idx += NW * 32) {
        int k = idx >> 4, m = idx & 15;
        ws2T[m * 36 + k] = Ws2[idx];
    }
    for (int idx = tid; idx < 192; idx += NW * 32) {
        int k3 = idx / 6, f3 = idx - k3 * 6;
        wd3F[f3 * 36 + k3] = Wd3[idx];
    }
    if (tid < 32) {
        we2S[tid] = We2[tid];
        bd1S[tid] = bd1[tid]; bd2S[tid] = bd2[tid]; bs1S[tid] = bs1[tid];
    }
    if (tid < 16) { bs2S[tid] = bs2[tid]; ws3S[tid] = Ws3[tid]; }
    if (tid < 6)  { bd3S[tid] = bd3[tid]; }
    if (tid == 0) { scal[0] = be2[0]; scal[1] = bs3[0]; }
    __syncthreads();

    const int lane = tid & 31;
    const int w = tid >> 5;
    float* A = act[w];

    const int i1 = lane / 6, j1 = lane - i1 * 6;   // element e = lane
    const int j2 = (lane < 4) ? lane + 2 : 2;      // element 32+lane -> (5, j2)

    // per-lane weight columns (coalesced / conflict-free, once per kernel)
    float wuC[6], wvC[6], wd1c[6];
#pragma unroll
    for (int f = 0; f < 6; f++) {
        wuC[f] = WuS[f * 32 + lane];
        wvC[f] = WvS[f * 32 + lane];
        wd1c[f] = Wd1[f * 32 + lane];
    }
    const float bul = buS[lane], bvl = bvS[lane];
    const float bd1l = bd1S[lane], bd2l = bd2S[lane], bs1l = bs1S[lane];
    const float bs2l = bs2S[lane & 15];
    const float ws3l = (lane < 16) ? ws3S[lane] : 0.0f;
    const float bd3l = bd3S[j1], bd3l2 = bd3S[j2];
    const float be2v = scal[0], bs3v = scal[1];

    const size_t predBase = (size_t)Btot * 36;
    const size_t scoreBase = (size_t)Btot * 72;

#pragma unroll 1
    for (int s = 0; s < SPW; s++) {
        const int b = (blockIdx.x * NW + w) * SPW + s;
        if (b < Btot) {
            // ---- stage factors into padded rows ----
            const float* fb = factors + (size_t)b * 36;
            A[FSP + i1 * 8 + j1] = fb[lane];
            if (lane < 4) A[FSP + 40 + j2] = fb[32 + lane];
            __syncwarp();

            // ---- u,v directly from factors via composed weights ----
#pragma unroll
            for (int i = 0; i < 6; i++) {
                float4 f4 = *(const float4*)&A[FSP + i * 8];
                float2 f2 = *(const float2*)&A[FSP + i * 8 + 4];
                float ui = bul, vi = bvl;
                DOT6S(ui, f4, f2, wuC);
                DOT6S(vi, f4, f2, wvC);
                A[AU + i * 36 + lane] = ui;
                A[AV + i * 36 + lane] = vi;
            }
            __syncwarp();

            // ---- adjacency (lane = edge): k-loop over hidden ----
            {
                float acc1 = 0.0f, acc2 = 0.0f;
#pragma unroll
                for (int t = 0; t < 8; t++) {
                    float4 w2 = *(const float4*)&we2S[4 * t];
                    float4 a1 = *(const float4*)&A[AU + i1 * 36 + 4 * t];
                    float4 b1 = *(const float4*)&A[AV + j1 * 36 + 4 * t];
                    acc1 = fmaf(fmaxf(a1.x + b1.x, 0.0f), w2.x, acc1);
                    acc1 = fmaf(fmaxf(a1.y + b1.y, 0.0f), w2.y, acc1);
                    acc1 = fmaf(fmaxf(a1.z + b1.z, 0.0f), w2.z, acc1);
                    acc1 = fmaf(fmaxf(a1.w + b1.w, 0.0f), w2.w, acc1);
                    float4 a2 = *(const float4*)&A[AU + 5 * 36 + 4 * t];
                    float4 b2 = *(const float4*)&A[AV + j2 * 36 + 4 * t];
                    acc2 = fmaf(fmaxf(a2.x + b2.x, 0.0f), w2.x, acc2);
                    acc2 = fmaf(fmaxf(a2.y + b2.y, 0.0f), w2.y, acc2);
                    acc2 = fmaf(fmaxf(a2.z + b2.z, 0.0f), w2.z, acc2);
                    acc2 = fmaf(fmaxf(a2.w + b2.w, 0.0f), w2.w, acc2);
                }
                float a1v = (i1 == j1) ? 0.0f : sigm(acc1 + be2v);
                float a2v = (lane == 3) ? 0.0f : sigm(acc2 + be2v);
                A[ADJ + i1 * 8 + j1] = a1v;
                out[(size_t)b * 36 + lane] = a1v;
                if (lane < 4) {
                    A[ADJ + 40 + j2] = a2v;
                    out[(size_t)b * 36 + 32 + lane] = a2v;
                }
            }
            __syncwarp();

            // ---- structured (lane = (n=i1, i=j1)): row dot6 ----
            {
                float4 ra4 = *(const float4*)&A[ADJ + j1 * 8];
                float2 ra2 = *(const float2*)&A[ADJ + j1 * 8 + 4];
                float4 rf4 = *(const float4*)&A[FSP + i1 * 8];
                float2 rf2 = *(const float2*)&A[FSP + i1 * 8 + 4];
                float sv = 0.0f;
                DOT6(sv, ra4, ra2, rf4, rf2);
                A[ASP + i1 * 8 + j1] = sv;
                if (lane < 4) {
                    float4 qa4 = *(const float4*)&A[ADJ + j2 * 8];
                    float2 qa2 = *(const float2*)&A[ADJ + j2 * 8 + 4];
                    float4 qf4 = *(const float4*)&A[FSP + 40];
                    float2 qf2 = *(const float2*)&A[FSP + 44];
                    float sv2 = 0.0f;
                    DOT6(sv2, qa4, qa2, qf4, qf2);
                    A[ASP + 40 + j2] = sv2;
                }
            }
            __syncwarp();

            // ---- h1 = relu(structured @ Wd1 + bd1) (lane = hidden) ----
#pragma unroll
            for (int n = 0; n < 6; n++) {
                float4 s4 = *(const float4*)&A[ASP + n * 8];
                float2 s2 = *(const float2*)&A[ASP + n * 8 + 4];
                float acc = bd1l;
                DOT6S(acc, s4, s2, wd1c);
                A[ANF + n * 32 + lane] = fmaxf(acc, 0.0f);
            }
            __syncwarp();

            // ---- h2 = relu(h1 @ Wd2 + bd2), interchanged ----
            {
                float acc[6];
#pragma unroll
                for (int n = 0; n < 6; n++) acc[n] = bd2l;
#pragma unroll
                for (int t = 0; t < 8; t++) {
                    float4 wv2 = *(const float4*)&wd2T[lane * 36 + 4 * t];
#pragma unroll
                    for (int n = 0; n < 6; n++) {
                        float4 hv = *(const float4*)&A[ANF + n * 32 + 4 * t];
                        FMA4V(acc[n], hv, wv2);
                    }
                }
#pragma unroll
                for (int n = 0; n < 6; n++)
                    A[AU + n * 36 + lane] = fmaxf(acc[n], 0.0f);
            }
            __syncwarp();

            // ---- pred (lane = (n=i1, f=j1)): k-loop over hidden ----
            {
                float acc1 = 0.0f, acc2 = 0.0f;
#pragma unroll
                for (int t = 0; t < 8; t++) {
                    float4 hv = *(const float4*)&A[AU + i1 * 36 + 4 * t];
                    float4 w3a = *(const float4*)&wd3F[j1 * 36 + 4 * t];
                    FMA4V(acc1, hv, w3a);
                    float4 h5 = *(const float4*)&A[AU + 5 * 36 + 4 * t];
                    float4 w3b = *(const float4*)&wd3F[j2 * 36 + 4 * t];
                    FMA4V(acc2, h5, w3b);
                }
                float p1 = acc1 + bd3l;
                float p2 = acc2 + bd3l2;
                A[ASP + i1 * 8 + j1] = p1;
                float* op = out + predBase + (size_t)b * 36;
                op[lane] = p1;
                if (lane < 4) {
                    A[ASP + 40 + j2] = p2;
                    op[32 + lane] = p2;
                }
            }
            __syncwarp();

            // ---- scorer layer 1 (lane = hidden) -> s1 in ANF ----
            {
                float ws1c[18];
#pragma unroll
                for (int t = 0; t < 4; t++) LD4(ws1T, ws1c + 4 * t, lane * 20 + 4 * t);
                {
                    float2 a = *(const float2*)&ws1T[lane * 20 + 16];
                    ws1c[16] = a.x; ws1c[17] = a.y;
                }
#pragma unroll
                for (int n = 0; n < 6; n++) {
                    float4 f4 = *(const float4*)&A[FSP + n * 8];
                    float2 f2 = *(const float2*)&A[FSP + n * 8 + 4];
                    float4 p4 = *(const float4*)&A[ASP + n * 8];
                    float2 p2 = *(const float2*)&A[ASP + n * 8 + 4];
                    float fk[6] = {f4.x, f4.y, f4.z, f4.w, f2.x, f2.y};
                    float pk[6] = {p4.x, p4.y, p4.z, p4.w, p2.x, p2.y};
                    float acc = bs1l;
#pragma unroll
                    for (int k = 0; k < 6; k++) {
                        acc = fmaf(fk[k], ws1c[k], acc);
                        acc = fmaf(pk[k], ws1c[6 + k], acc);
                        acc = fmaf(fabsf(fk[k] - pk[k]), ws1c[12 + k], acc);
                    }
                    A[ANF + n * 32 + lane] = fmaxf(acc, 0.0f);
                }
            }
            __syncwarp();

            // ---- scorer layers 2+3, interchanged ----
            float ssum = 0.0f;
            {
                float acc[6];
#pragma unroll
                for (int n = 0; n < 6; n++) acc[n] = bs2l;
#pragma unroll
                for (int t = 0; t < 8; t++) {
                    float4 wv2 = *(const float4*)&ws2T[(lane & 15) * 36 + 4 * t];
#pragma unroll
                    for (int n = 0; n < 6; n++) {
                        float4 sv = *(const float4*)&A[ANF + n * 32 + 4 * t];
                        FMA4V(acc[n], sv, wv2);
                    }
                }
#pragma unroll
                for (int n = 0; n < 6; n++) {
                    float tt = fmaxf(acc[n], 0.0f) * ws3l;  // lanes >= 16 contribute 0
                    ssum += sigm(wsum(tt) + bs3v);
                }
            }
            if (lane == 0) out[scoreBase + b] = ssum * (1.0f / 6.0f);
            __syncwarp();
        }
    }
}

extern "C" void kernel_launch(void* const* d_in, const int* in_sizes, int n_in,
                              void* d_out, int out_size) {
    const float* p[19];
    for (int i = 0; i < 19; i++) p[i] = (const float*)d_in[i];
    int Btot = in_sizes[0] / 36;
    int per_block = NW * SPW;
    int blocks = (Btot + per_block - 1) / per_block;
    cad_kernel<<<blocks, NW * 32>>>(
        p[0], p[1], p[2], p[3], p[4], p[5], p[6], p[7], p[8], p[9], p[10],
        p[11], p[12], p[13], p[14], p[15], p[16], p[17], p[18],
        (float*)d_out, Btot);
}

// round 10
// speedup vs baseline: 1.2594x; 1.0305x over previous
#include <cuda_runtime.h>

#define FULL 0xffffffffu
constexpr int NW = 8;    // warps per block
constexpr int SPW = 8;   // samples per warp

// per-warp activation region offsets (floats); all 16B-aligned
constexpr int FSP = 0;    // factors, 6 rows stride 8 (48)
constexpr int ANF = 48;   // h1 / s1, i*32+lane (192)
constexpr int AU  = 240;  // u / h2, 6 rows stride 36
constexpr int AV  = 464;  // v, 6 rows stride 36
constexpr int ADJ = 680;  // adjacency, rows stride 8 (48)
constexpr int ASP = 728;  // structured / pred, rows stride 8 (48)
constexpr int ACT = 784;

__device__ __forceinline__ float sigm(float x) { return 1.0f / (1.0f + __expf(-x)); }

__device__ __forceinline__ float wsum(float t) {
#pragma unroll
    for (int o = 16; o; o >>= 1) t += __shfl_xor_sync(FULL, t, o);
    return t;
}

#define FMA4V(acc, vec, wv)                        \
    acc = fmaf((vec).x, (wv).x, acc);              \
    acc = fmaf((vec).y, (wv).y, acc);              \
    acc = fmaf((vec).z, (wv).z, acc);              \
    acc = fmaf((vec).w, (wv).w, acc);

#define LD4(arr, dst, off)                                        \
    { float4 _a = *(const float4*)&(arr)[off];                    \
      (dst)[0] = _a.x; (dst)[1] = _a.y; (dst)[2] = _a.z; (dst)[3] = _a.w; }

// dot6: row (float4,float2) against 6 scalar weights
#define DOT6S(acc, r4, r2, wc)                     \
    acc = fmaf((r4).x, (wc)[0], acc);              \
    acc = fmaf((r4).y, (wc)[1], acc);              \
    acc = fmaf((r4).z, (wc)[2], acc);              \
    acc = fmaf((r4).w, (wc)[3], acc);              \
    acc = fmaf((r2).x, (wc)[4], acc);              \
    acc = fmaf((r2).y, (wc)[5], acc);

#define DOT6(acc, r4, r2, q4, q2)                  \
    acc = fmaf((r4).x, (q4).x, acc);               \
    acc = fmaf((r4).y, (q4).y, acc);               \
    acc = fmaf((r4).z, (q4).z, acc);               \
    acc = fmaf((r4).w, (q4).w, acc);               \
    acc = fmaf((r2).x, (q2).x, acc);               \
    acc = fmaf((r2).y, (q2).y, acc);

__global__ __launch_bounds__(NW * 32, 4) void cad_kernel(
    const float* __restrict__ factors,
    const float* __restrict__ Wn,  const float* __restrict__ bn,
    const float* __restrict__ We1, const float* __restrict__ be1,
    const float* __restrict__ We2, const float* __restrict__ be2,
    const float* __restrict__ Wd1, const float* __restrict__ bd1,
    const float* __restrict__ Wd2, const float* __restrict__ bd2,
    const float* __restrict__ Wd3, const float* __restrict__ bd3,
    const float* __restrict__ Ws1, const float* __restrict__ bs1,
    const float* __restrict__ Ws2, const float* __restrict__ bs2,
    const float* __restrict__ Ws3, const float* __restrict__ bs3,
    float* __restrict__ out, int Btot)
{
    // composed edge-layer weights: Wu = Wn@We1[:32], Wv = Wn@We1[32:]
    __shared__ __align__(16) float WuS[192], WvS[192];
    __shared__ __align__(16) float wd1S[192];
    __shared__ __align__(16) float buS[32], bvS[32];
    __shared__ __align__(16) float wd2T[32 * 36];
    __shared__ __align__(16) float wd3F[6 * 36];
    __shared__ __align__(16) float ws1T[32 * 20];
    __shared__ __align__(16) float ws2T[16 * 36];
    __shared__ __align__(16) float we2S[32];
    __shared__ float bd1S[32], bd2S[32], bs1S[32];
    __shared__ float bs2S[16], ws3S[16], bd3S[8], scal[2];
    __shared__ __align__(16) float act[NW][ACT];

    const int tid = threadIdx.x;

    // ---- composition: Wu[f][h] = sum_k Wn[f][k]*We1[k][h]; Wv with We1[32+k] ----
    if (tid < 192) {
        int f = tid >> 5, h = tid & 31;
        float au = 0.0f, av = 0.0f;
#pragma unroll 4
        for (int k = 0; k < 32; k++) {
            float wn = Wn[f * 32 + k];
            au = fmaf(wn, We1[k * 32 + h], au);
            av = fmaf(wn, We1[(32 + k) * 32 + h], av);
        }
        WuS[f * 32 + h] = au;
        WvS[f * 32 + h] = av;
        wd1S[f * 32 + h] = Wd1[f * 32 + h];
    }
    if (tid < 32) {
        float bu = be1[tid], bv = 0.0f;
#pragma unroll 4
        for (int k = 0; k < 32; k++) {
            float b = bn[k];
            bu = fmaf(b, We1[k * 32 + tid], bu);
            bv = fmaf(b, We1[(32 + k) * 32 + tid], bv);
        }
        buS[tid] = bu; bvS[tid] = bv;
    }
    // ---- other weight staging / transposes ----
    for (int idx = tid; idx < 1024; idx += NW * 32) {
        int k = idx >> 5, l = idx & 31;
        wd2T[l * 36 + k] = Wd2[idx];
    }
    for (int idx = tid; idx < 576; idx += NW * 32) {
        int k = idx >> 5, l = idx & 31;
        ws1T[l * 20 + k] = Ws1[idx];
    }
    for (int idx = tid; idx < 512; idx += NW * 32) {
        int k = idx >> 4, m = idx & 15;
        ws2T[m * 36 + k] = Ws2[idx];
    }
    for (int idx = tid; idx < 192; idx += NW * 32) {
        int k3 = idx / 6, f3 = idx - k3 * 6;
        wd3F[f3 * 36 + k3] = Wd3[idx];
    }
    if (tid < 32) {
        we2S[tid] = We2[tid];
        bd1S[tid] = bd1[tid]; bd2S[tid] = bd2[tid]; bs1S[tid] = bs1[tid];
    }
    if (tid < 16) { bs2S[tid] = bs2[tid]; ws3S[tid] = Ws3[tid]; }
    if (tid < 6)  { bd3S[tid] = bd3[tid]; }
    if (tid == 0) { scal[0] = be2[0]; scal[1] = bs3[0]; }
    __syncthreads();

    const int lane = tid & 31;
    const int w = tid >> 5;
    float* A = act[w];

    const int i1 = lane / 6, j1 = lane - i1 * 6;   // element e = lane
    const int j2 = (lane < 4) ? lane + 2 : 2;      // element 32+lane -> (5, j2)

    const float bd2l = bd2S[lane], bs1l = bs1S[lane];
    const float bs2l = bs2S[lane & 15];
    const float ws3l = (lane < 16) ? ws3S[lane] : 0.0f;
    const float bd3l = bd3S[j1], bd3l2 = bd3S[j2];
    const float be2v = scal[0], bs3v = scal[1];

    const size_t predBase = (size_t)Btot * 36;
    const size_t scoreBase = (size_t)Btot * 72;

#pragma unroll 1
    for (int s = 0; s < SPW; s++) {
        const int b = (blockIdx.x * NW + w) * SPW + s;
        if (b < Btot) {
            // ---- stage factors into padded rows ----
            const float* fb = factors + (size_t)b * 36;
            A[FSP + i1 * 8 + j1] = fb[lane];
            if (lane < 4) A[FSP + 40 + j2] = fb[32 + lane];
            __syncwarp();

            // ---- u,v directly from factors via composed weights (per-stage loads) ----
            {
                float wuC[6], wvC[6];
#pragma unroll
                for (int f = 0; f < 6; f++) {
                    wuC[f] = WuS[f * 32 + lane];
                    wvC[f] = WvS[f * 32 + lane];
                }
                float bul = buS[lane], bvl = bvS[lane];
#pragma unroll
                for (int i = 0; i < 6; i++) {
                    float4 f4 = *(const float4*)&A[FSP + i * 8];
                    float2 f2 = *(const float2*)&A[FSP + i * 8 + 4];
                    float ui = bul, vi = bvl;
                    DOT6S(ui, f4, f2, wuC);
                    DOT6S(vi, f4, f2, wvC);
                    A[AU + i * 36 + lane] = ui;
                    A[AV + i * 36 + lane] = vi;
                }
            }
            __syncwarp();

            // ---- adjacency (lane = edge): k-loop over hidden ----
            {
                float acc1 = 0.0f, acc2 = 0.0f;
#pragma unroll
                for (int t = 0; t < 8; t++) {
                    float4 w2 = *(const float4*)&we2S[4 * t];
                    float4 a1 = *(const float4*)&A[AU + i1 * 36 + 4 * t];
                    float4 b1 = *(const float4*)&A[AV + j1 * 36 + 4 * t];
                    acc1 = fmaf(fmaxf(a1.x + b1.x, 0.0f), w2.x, acc1);
                    acc1 = fmaf(fmaxf(a1.y + b1.y, 0.0f), w2.y, acc1);
                    acc1 = fmaf(fmaxf(a1.z + b1.z, 0.0f), w2.z, acc1);
                    acc1 = fmaf(fmaxf(a1.w + b1.w, 0.0f), w2.w, acc1);
                    float4 a2 = *(const float4*)&A[AU + 5 * 36 + 4 * t];
                    float4 b2 = *(const float4*)&A[AV + j2 * 36 + 4 * t];
                    acc2 = fmaf(fmaxf(a2.x + b2.x, 0.0f), w2.x, acc2);
                    acc2 = fmaf(fmaxf(a2.y + b2.y, 0.0f), w2.y, acc2);
                    acc2 = fmaf(fmaxf(a2.z + b2.z, 0.0f), w2.z, acc2);
                    acc2 = fmaf(fmaxf(a2.w + b2.w, 0.0f), w2.w, acc2);
                }
                float a1v = (i1 == j1) ? 0.0f : sigm(acc1 + be2v);
                float a2v = (lane == 3) ? 0.0f : sigm(acc2 + be2v);
                A[ADJ + i1 * 8 + j1] = a1v;
                out[(size_t)b * 36 + lane] = a1v;
                if (lane < 4) {
                    A[ADJ + 40 + j2] = a2v;
                    out[(size_t)b * 36 + 32 + lane] = a2v;
                }
            }
            __syncwarp();

            // ---- structured (lane = (n=i1, i=j1)): row dot6 ----
            {
                float4 ra4 = *(const float4*)&A[ADJ + j1 * 8];
                float2 ra2 = *(const float2*)&A[ADJ + j1 * 8 + 4];
                float4 rf4 = *(const float4*)&A[FSP + i1 * 8];
                float2 rf2 = *(const float2*)&A[FSP + i1 * 8 + 4];
                float sv = 0.0f;
                DOT6(sv, ra4, ra2, rf4, rf2);
                A[ASP + i1 * 8 + j1] = sv;
                if (lane < 4) {
                    float4 qa4 = *(const float4*)&A[ADJ + j2 * 8];
                    float2 qa2 = *(const float2*)&A[ADJ + j2 * 8 + 4];
                    float4 qf4 = *(const float4*)&A[FSP + 40];
                    float2 qf2 = *(const float2*)&A[FSP + 44];
                    float sv2 = 0.0f;
                    DOT6(sv2, qa4, qa2, qf4, qf2);
                    A[ASP + 40 + j2] = sv2;
                }
            }
            __syncwarp();

            // ---- h1 = relu(structured @ Wd1 + bd1) (lane = hidden) ----
            {
                float wd1c[6];
#pragma unroll
                for (int f = 0; f < 6; f++) wd1c[f] = wd1S[f * 32 + lane];
                float bd1l = bd1S[lane];
#pragma unroll
                for (int n = 0; n < 6; n++) {
                    float4 s4 = *(const float4*)&A[ASP + n * 8];
                    float2 s2 = *(const float2*)&A[ASP + n * 8 + 4];
                    float acc = bd1l;
                    DOT6S(acc, s4, s2, wd1c);
                    A[ANF + n * 32 + lane] = fmaxf(acc, 0.0f);
                }
            }
            __syncwarp();

            // ---- h2 = relu(h1 @ Wd2 + bd2), interchanged ----
            {
                float acc[6];
#pragma unroll
                for (int n = 0; n < 6; n++) acc[n] = bd2l;
#pragma unroll
                for (int t = 0; t < 8; t++) {
                    float4 wv2 = *(const float4*)&wd2T[lane * 36 + 4 * t];
#pragma unroll
                    for (int n = 0; n < 6; n++) {
                        float4 hv = *(const float4*)&A[ANF + n * 32 + 4 * t];
                        FMA4V(acc[n], hv, wv2);
                    }
                }
#pragma unroll
                for (int n = 0; n < 6; n++)
                    A[AU + n * 36 + lane] = fmaxf(acc[n], 0.0f);
            }
            __syncwarp();

            // ---- pred (lane = (n=i1, f=j1)): k-loop over hidden ----
            {
                float acc1 = 0.0f, acc2 = 0.0f;
#pragma unroll
                for (int t = 0; t < 8; t++) {
                    float4 hv = *(const float4*)&A[AU + i1 * 36 + 4 * t];
                    float4 w3a = *(const float4*)&wd3F[j1 * 36 + 4 * t];
                    FMA4V(acc1, hv, w3a);
                    float4 h5 = *(const float4*)&A[AU + 5 * 36 + 4 * t];
                    float4 w3b = *(const float4*)&wd3F[j2 * 36 + 4 * t];
                    FMA4V(acc2, h5, w3b);
                }
                float p1 = acc1 + bd3l;
                float p2 = acc2 + bd3l2;
                A[ASP + i1 * 8 + j1] = p1;
                float* op = out + predBase + (size_t)b * 36;
                op[lane] = p1;
                if (lane < 4) {
                    A[ASP + 40 + j2] = p2;
                    op[32 + lane] = p2;
                }
            }
            __syncwarp();

            // ---- scorer layer 1 (lane = hidden) -> s1 in ANF ----
            {
                float ws1c[18];
#pragma unroll
                for (int t = 0; t < 4; t++) LD4(ws1T, ws1c + 4 * t, lane * 20 + 4 * t);
                {
                    float2 a = *(const float2*)&ws1T[lane * 20 + 16];
                    ws1c[16] = a.x; ws1c[17] = a.y;
                }
#pragma unroll
                for (int n = 0; n < 6; n++) {
                    float4 f4 = *(const float4*)&A[FSP + n * 8];
                    float2 f2 = *(const float2*)&A[FSP + n * 8 + 4];
                    float4 p4 = *(const float4*)&A[ASP + n * 8];
                    float2 p2 = *(const float2*)&A[ASP + n * 8 + 4];
                    float fk[6] = {f4.x, f4.y, f4.z, f4.w, f2.x, f2.y};
                    float pk[6] = {p4.x, p4.y, p4.z, p4.w, p2.x, p2.y};
                    float acc = bs1l;
#pragma unroll
                    for (int k = 0; k < 6; k++) {
                        acc = fmaf(fk[k], ws1c[k], acc);
                        acc = fmaf(pk[k], ws1c[6 + k], acc);
                        acc = fmaf(fabsf(fk[k] - pk[k]), ws1c[12 + k], acc);
                    }
                    A[ANF + n * 32 + lane] = fmaxf(acc, 0.0f);
                }
            }
            __syncwarp();

            // ---- scorer layers 2+3, interchanged ----
            float ssum = 0.0f;
            {
                float acc[6];
#pragma unroll
                for (int n = 0; n < 6; n++) acc[n] = bs2l;
#pragma unroll
                for (int t = 0; t < 8; t++) {
                    float4 wv2 = *(const float4*)&ws2T[(lane & 15) * 36 + 4 * t];
#pragma unroll
                    for (int n = 0; n < 6; n++) {
                        float4 sv = *(const float4*)&A[ANF + n * 32 + 4 * t];
                        FMA4V(acc[n], sv, wv2);
                    }
                }
#pragma unroll
                for (int n = 0; n < 6; n++) {
                    float tt = fmaxf(acc[n], 0.0f) * ws3l;  // lanes >= 16 contribute 0
                    ssum += sigm(wsum(tt) + bs3v);
                }
            }
            if (lane == 0) out[scoreBase + b] = ssum * (1.0f / 6.0f);
            __syncwarp();
        }
    }
}

extern "C" void kernel_launch(void* const* d_in, const int* in_sizes, int n_in,
                              void* d_out, int out_size) {
    const float* p[19];
    for (int i = 0; i < 19; i++) p[i] = (const float*)d_in[i];
    int Btot = in_sizes[0] / 36;
    int per_block = NW * SPW;
    int blocks = (Btot + per_block - 1) / per_block;
    cad_kernel<<<blocks, NW * 32>>>(
        p[0], p[1], p[2], p[3], p[4], p[5], p[6], p[7], p[8], p[9], p[10],
        p[11], p[12], p[13], p[14], p[15], p[16], p[17], p[18],
        (float*)d_out, Btot);
}

// round 11
// speedup vs baseline: 1.3332x; 1.0586x over previous
#include <cuda_runtime.h>

#define FULL 0xffffffffu
constexpr int NW = 8;     // warps per block
constexpr int SPW = 8;    // samples per warp
constexpr int PAIRS = SPW / 2;

// per-sample-slot activation offsets (floats); ANF overlays AV (AV dead after adjacency)
constexpr int FSP = 0;    // factors, 6 rows stride 8 (48)
constexpr int AU  = 48;   // u / h2, 6 rows stride 36 (224)
constexpr int AV  = 272;  // v (224); ANF = h1/s1 overlays here (192)
constexpr int ANF = 272;
constexpr int ADJ = 496;  // adjacency rows stride 8 (48)
constexpr int ASP = 544;  // structured / pred rows stride 8 (48)
constexpr int ACT = 592;

__device__ __forceinline__ float sigm(float x) { return 1.0f / (1.0f + __expf(-x)); }

// 16-lane reduction (lanes >= 16 must hold 0)
__device__ __forceinline__ float wsum16(float t) {
#pragma unroll
    for (int o = 8; o; o >>= 1) t += __shfl_xor_sync(FULL, t, o);
    return t;
}

#define FMA4V(acc, vec, wv)                        \
    acc = fmaf((vec).x, (wv).x, acc);              \
    acc = fmaf((vec).y, (wv).y, acc);              \
    acc = fmaf((vec).z, (wv).z, acc);              \
    acc = fmaf((vec).w, (wv).w, acc);

#define LD4(arr, dst, off)                                        \
    { float4 _a = *(const float4*)&(arr)[off];                    \
      (dst)[0] = _a.x; (dst)[1] = _a.y; (dst)[2] = _a.z; (dst)[3] = _a.w; }

#define DOT6S(acc, r4, r2, wc)                     \
    acc = fmaf((r4).x, (wc)[0], acc);              \
    acc = fmaf((r4).y, (wc)[1], acc);              \
    acc = fmaf((r4).z, (wc)[2], acc);              \
    acc = fmaf((r4).w, (wc)[3], acc);              \
    acc = fmaf((r2).x, (wc)[4], acc);              \
    acc = fmaf((r2).y, (wc)[5], acc);

#define DOT6(acc, r4, r2, q4, q2)                  \
    acc = fmaf((r4).x, (q4).x, acc);               \
    acc = fmaf((r4).y, (q4).y, acc);               \
    acc = fmaf((r4).z, (q4).z, acc);               \
    acc = fmaf((r4).w, (q4).w, acc);               \
    acc = fmaf((r2).x, (q2).x, acc);               \
    acc = fmaf((r2).y, (q2).y, acc);

__global__ __launch_bounds__(NW * 32, 3) void cad_kernel(
    const float* __restrict__ factors,
    const float* __restrict__ Wn,  const float* __restrict__ bn,
    const float* __restrict__ We1, const float* __restrict__ be1,
    const float* __restrict__ We2, const float* __restrict__ be2,
    const float* __restrict__ Wd1, const float* __restrict__ bd1,
    const float* __restrict__ Wd2, const float* __restrict__ bd2,
    const float* __restrict__ Wd3, const float* __restrict__ bd3,
    const float* __restrict__ Ws1, const float* __restrict__ bs1,
    const float* __restrict__ Ws2, const float* __restrict__ bs2,
    const float* __restrict__ Ws3, const float* __restrict__ bs3,
    float* __restrict__ out, int Btot)
{
    __shared__ __align__(16) float WuS[192], WvS[192];
    __shared__ __align__(16) float wd1S[192];
    __shared__ __align__(16) float buS[32], bvS[32];
    __shared__ __align__(16) float wd2T[32 * 36];
    __shared__ __align__(16) float wd3F[6 * 36];
    __shared__ __align__(16) float ws1T[32 * 20];
    __shared__ __align__(16) float ws2T[16 * 36];
    __shared__ __align__(16) float we2S[32];
    __shared__ float bd1S[32], bd2S[32], bs1S[32];
    __shared__ float bs2S[16], ws3S[16], bd3S[8], scal[2];
    __shared__ __align__(16) float act[NW][2][ACT];

    const int tid = threadIdx.x;

    // ---- composed edge weights: Wu = Wn@We1[:32], Wv = Wn@We1[32:] ----
    if (tid < 192) {
        int f = tid >> 5, h = tid & 31;
        float au = 0.0f, av = 0.0f;
#pragma unroll 4
        for (int k = 0; k < 32; k++) {
            float wn = Wn[f * 32 + k];
            au = fmaf(wn, We1[k * 32 + h], au);
            av = fmaf(wn, We1[(32 + k) * 32 + h], av);
        }
        WuS[f * 32 + h] = au;
        WvS[f * 32 + h] = av;
        wd1S[f * 32 + h] = Wd1[f * 32 + h];
    }
    if (tid < 32) {
        float bu = be1[tid], bv = 0.0f;
#pragma unroll 4
        for (int k = 0; k < 32; k++) {
            float b = bn[k];
            bu = fmaf(b, We1[k * 32 + tid], bu);
            bv = fmaf(b, We1[(32 + k) * 32 + tid], bv);
        }
        buS[tid] = bu; bvS[tid] = bv;
    }
    for (int idx = tid; idx < 1024; idx += NW * 32) {
        int k = idx >> 5, l = idx & 31;
        wd2T[l * 36 + k] = Wd2[idx];
    }
    for (int idx = tid; idx < 576; idx += NW * 32) {
        int k = idx >> 5, l = idx & 31;
        ws1T[l * 20 + k] = Ws1[idx];
    }
    for (int idx = tid; idx < 512; idx += NW * 32) {
        int k = idx >> 4, m = idx & 15;
        ws2T[m * 36 + k] = Ws2[idx];
    }
    for (int idx = tid; idx < 192; idx += NW * 32) {
        int k3 = idx / 6, f3 = idx - k3 * 6;
        wd3F[f3 * 36 + k3] = Wd3[idx];
    }
    if (tid < 32) {
        we2S[tid] = We2[tid];
        bd1S[tid] = bd1[tid]; bd2S[tid] = bd2[tid]; bs1S[tid] = bs1[tid];
    }
    if (tid < 16) { bs2S[tid] = bs2[tid]; ws3S[tid] = Ws3[tid]; }
    if (tid < 6)  { bd3S[tid] = bd3[tid]; }
    if (tid == 0) { scal[0] = be2[0]; scal[1] = bs3[0]; }
    __syncthreads();

    const int lane = tid & 31;
    const int w = tid >> 5;

    const int i1 = lane / 6, j1 = lane - i1 * 6;   // element e = lane
    const int j2 = (lane < 4) ? lane + 2 : 2;      // element 32+lane -> (5, j2)

    const float bd2l = bd2S[lane], bs1l = bs1S[lane];
    const float bs2l = bs2S[lane & 15];
    const float ws3l = (lane < 16) ? ws3S[lane] : 0.0f;
    const float bd3l = bd3S[j1], bd3l2 = bd3S[j2];
    const float be2v = scal[0], bs3v = scal[1];

    const size_t predBase = (size_t)Btot * 36;
    const size_t scoreBase = (size_t)Btot * 72;

#pragma unroll 1
    for (int it = 0; it < PAIRS; it++) {
        const int b0 = ((blockIdx.x * NW + w) * SPW) + 2 * it;
        if (b0 < Btot) {
            const bool v1 = (b0 + 1) < Btot;
            int bb[2] = {b0, v1 ? b0 + 1 : b0};

            // ---- stage factors ----
#pragma unroll
            for (int p = 0; p < 2; p++) {
                float* A = act[w][p];
                const float* fb = factors + (size_t)bb[p] * 36;
                A[FSP + i1 * 8 + j1] = fb[lane];
                if (lane < 4) A[FSP + 40 + j2] = fb[32 + lane];
            }
            __syncwarp();

            // ---- u,v via composed weights (weights loaded once per pair) ----
            {
                float wuC[6], wvC[6];
#pragma unroll
                for (int f = 0; f < 6; f++) {
                    wuC[f] = WuS[f * 32 + lane];
                    wvC[f] = WvS[f * 32 + lane];
                }
                float bul = buS[lane], bvl = bvS[lane];
#pragma unroll
                for (int p = 0; p < 2; p++) {
                    float* A = act[w][p];
#pragma unroll
                    for (int i = 0; i < 6; i++) {
                        float4 f4 = *(const float4*)&A[FSP + i * 8];
                        float2 f2 = *(const float2*)&A[FSP + i * 8 + 4];
                        float ui = bul, vi = bvl;
                        DOT6S(ui, f4, f2, wuC);
                        DOT6S(vi, f4, f2, wvC);
                        A[AU + i * 36 + lane] = ui;
                        A[AV + i * 36 + lane] = vi;
                    }
                }
            }
            __syncwarp();

            // ---- adjacency (lane = edge); we2 read once per t, both samples ----
            {
                float acc1[2] = {0.0f, 0.0f}, acc2[2] = {0.0f, 0.0f};
#pragma unroll
                for (int t = 0; t < 8; t++) {
                    float4 w2 = *(const float4*)&we2S[4 * t];
#pragma unroll
                    for (int p = 0; p < 2; p++) {
                        float* A = act[w][p];
                        float4 a1 = *(const float4*)&A[AU + i1 * 36 + 4 * t];
                        float4 b1 = *(const float4*)&A[AV + j1 * 36 + 4 * t];
                        acc1[p] = fmaf(fmaxf(a1.x + b1.x, 0.0f), w2.x, acc1[p]);
                        acc1[p] = fmaf(fmaxf(a1.y + b1.y, 0.0f), w2.y, acc1[p]);
                        acc1[p] = fmaf(fmaxf(a1.z + b1.z, 0.0f), w2.z, acc1[p]);
                        acc1[p] = fmaf(fmaxf(a1.w + b1.w, 0.0f), w2.w, acc1[p]);
                        float4 a2 = *(const float4*)&A[AU + 5 * 36 + 4 * t];
                        float4 b2 = *(const float4*)&A[AV + j2 * 36 + 4 * t];
                        acc2[p] = fmaf(fmaxf(a2.x + b2.x, 0.0f), w2.x, acc2[p]);
                        acc2[p] = fmaf(fmaxf(a2.y + b2.y, 0.0f), w2.y, acc2[p]);
                        acc2[p] = fmaf(fmaxf(a2.z + b2.z, 0.0f), w2.z, acc2[p]);
                        acc2[p] = fmaf(fmaxf(a2.w + b2.w, 0.0f), w2.w, acc2[p]);
                    }
                }
#pragma unroll
                for (int p = 0; p < 2; p++) {
                    float* A = act[w][p];
                    float a1v = (i1 == j1) ? 0.0f : sigm(acc1[p] + be2v);
                    float a2v = (lane == 3) ? 0.0f : sigm(acc2[p] + be2v);
                    A[ADJ + i1 * 8 + j1] = a1v;
                    if (lane < 4) A[ADJ + 40 + j2] = a2v;
                    if (p == 0 || v1) {
                        out[(size_t)bb[p] * 36 + lane] = a1v;
                        if (lane < 4) out[(size_t)bb[p] * 36 + 32 + lane] = a2v;
                    }
                }
            }
            __syncwarp();

            // ---- structured (lane = (n=i1, i=j1)) ----
#pragma unroll
            for (int p = 0; p < 2; p++) {
                float* A = act[w][p];
                float4 ra4 = *(const float4*)&A[ADJ + j1 * 8];
                float2 ra2 = *(const float2*)&A[ADJ + j1 * 8 + 4];
                float4 rf4 = *(const float4*)&A[FSP + i1 * 8];
                float2 rf2 = *(const float2*)&A[FSP + i1 * 8 + 4];
                float sv = 0.0f;
                DOT6(sv, ra4, ra2, rf4, rf2);
                A[ASP + i1 * 8 + j1] = sv;
                if (lane < 4) {
                    float4 qa4 = *(const float4*)&A[ADJ + j2 * 8];
                    float2 qa2 = *(const float2*)&A[ADJ + j2 * 8 + 4];
                    float4 qf4 = *(const float4*)&A[FSP + 40];
                    float2 qf2 = *(const float2*)&A[FSP + 44];
                    float sv2 = 0.0f;
                    DOT6(sv2, qa4, qa2, qf4, qf2);
                    A[ASP + 40 + j2] = sv2;
                }
            }
            __syncwarp();

            // ---- h1 (lane = hidden); wd1 loaded once per pair ----
            {
                float wd1c[6];
#pragma unroll
                for (int f = 0; f < 6; f++) wd1c[f] = wd1S[f * 32 + lane];
                float bd1l = bd1S[lane];
#pragma unroll
                for (int p = 0; p < 2; p++) {
                    float* A = act[w][p];
#pragma unroll
                    for (int n = 0; n < 6; n++) {
                        float4 s4 = *(const float4*)&A[ASP + n * 8];
                        float2 s2 = *(const float2*)&A[ASP + n * 8 + 4];
                        float acc = bd1l;
                        DOT6S(acc, s4, s2, wd1c);
                        A[ANF + n * 32 + lane] = fmaxf(acc, 0.0f);
                    }
                }
            }
            __syncwarp();

            // ---- h2 interchanged; wd2 quad read once per t, both samples ----
            {
                float acc[2][6];
#pragma unroll
                for (int p = 0; p < 2; p++)
#pragma unroll
                    for (int n = 0; n < 6; n++) acc[p][n] = bd2l;
#pragma unroll
                for (int t = 0; t < 8; t++) {
                    float4 wv2 = *(const float4*)&wd2T[lane * 36 + 4 * t];
#pragma unroll
                    for (int p = 0; p < 2; p++) {
                        float* A = act[w][p];
#pragma unroll
                        for (int n = 0; n < 6; n++) {
                            float4 hv = *(const float4*)&A[ANF + n * 32 + 4 * t];
                            FMA4V(acc[p][n], hv, wv2);
                        }
                    }
                }
#pragma unroll
                for (int p = 0; p < 2; p++) {
                    float* A = act[w][p];
#pragma unroll
                    for (int n = 0; n < 6; n++)
                        A[AU + n * 36 + lane] = fmaxf(acc[p][n], 0.0f);
                }
            }
            __syncwarp();

            // ---- pred; wd3 quads read once per t ----
            {
                float pa[2] = {0.0f, 0.0f}, pb[2] = {0.0f, 0.0f};
#pragma unroll
                for (int t = 0; t < 8; t++) {
                    float4 w3a = *(const float4*)&wd3F[j1 * 36 + 4 * t];
                    float4 w3b = *(const float4*)&wd3F[j2 * 36 + 4 * t];
#pragma unroll
                    for (int p = 0; p < 2; p++) {
                        float* A = act[w][p];
                        float4 hv = *(const float4*)&A[AU + i1 * 36 + 4 * t];
                        FMA4V(pa[p], hv, w3a);
                        float4 h5 = *(const float4*)&A[AU + 5 * 36 + 4 * t];
                        FMA4V(pb[p], h5, w3b);
                    }
                }
#pragma unroll
                for (int p = 0; p < 2; p++) {
                    float* A = act[w][p];
                    float p1 = pa[p] + bd3l;
                    float p2 = pb[p] + bd3l2;
                    A[ASP + i1 * 8 + j1] = p1;
                    if (lane < 4) A[ASP + 40 + j2] = p2;
                    if (p == 0 || v1) {
                        float* op = out + predBase + (size_t)bb[p] * 36;
                        op[lane] = p1;
                        if (lane < 4) op[32 + lane] = p2;
                    }
                }
            }
            __syncwarp();

            // ---- scorer layer 1; ws1 loaded once per pair ----
            {
                float ws1c[18];
#pragma unroll
                for (int t = 0; t < 4; t++) LD4(ws1T, ws1c + 4 * t, lane * 20 + 4 * t);
                {
                    float2 a = *(const float2*)&ws1T[lane * 20 + 16];
                    ws1c[16] = a.x; ws1c[17] = a.y;
                }
#pragma unroll
                for (int p = 0; p < 2; p++) {
                    float* A = act[w][p];
#pragma unroll
                    for (int n = 0; n < 6; n++) {
                        float4 f4 = *(const float4*)&A[FSP + n * 8];
                        float2 f2 = *(const float2*)&A[FSP + n * 8 + 4];
                        float4 p4 = *(const float4*)&A[ASP + n * 8];
                        float2 p2 = *(const float2*)&A[ASP + n * 8 + 4];
                        float fk[6] = {f4.x, f4.y, f4.z, f4.w, f2.x, f2.y};
                        float pk[6] = {p4.x, p4.y, p4.z, p4.w, p2.x, p2.y};
                        float acc = bs1l;
#pragma unroll
                        for (int k = 0; k < 6; k++) {
                            acc = fmaf(fk[k], ws1c[k], acc);
                            acc = fmaf(pk[k], ws1c[6 + k], acc);
                            acc = fmaf(fabsf(fk[k] - pk[k]), ws1c[12 + k], acc);
                        }
                        A[ANF + n * 32 + lane] = fmaxf(acc, 0.0f);
                    }
                }
            }
            __syncwarp();

            // ---- scorer layers 2+3; ws2 quad once per t ----
            {
                float acc[2][6];
#pragma unroll
                for (int p = 0; p < 2; p++)
#pragma unroll
                    for (int n = 0; n < 6; n++) acc[p][n] = bs2l;
#pragma unroll
                for (int t = 0; t < 8; t++) {
                    float4 wv2 = *(const float4*)&ws2T[(lane & 15) * 36 + 4 * t];
#pragma unroll
                    for (int p = 0; p < 2; p++) {
                        float* A = act[w][p];
#pragma unroll
                        for (int n = 0; n < 6; n++) {
                            float4 sv = *(const float4*)&A[ANF + n * 32 + 4 * t];
                            FMA4V(acc[p][n], sv, wv2);
                        }
                    }
                }
#pragma unroll
                for (int p = 0; p < 2; p++) {
                    float ssum = 0.0f;
#pragma unroll
                    for (int n = 0; n < 6; n++) {
                        float tt = fmaxf(acc[p][n], 0.0f) * ws3l;  // lanes >= 16: 0
                        ssum += sigm(wsum16(tt) + bs3v);
                    }
                    if (lane == 0 && (p == 0 || v1))
                        out[scoreBase + bb[p]] = ssum * (1.0f / 6.0f);
                }
            }
            __syncwarp();
        }
    }
}

extern "C" void kernel_launch(void* const* d_in, const int* in_sizes, int n_in,
                              void* d_out, int out_size) {
    const float* p[19];
    for (int i = 0; i < 19; i++) p[i] = (const float*)d_in[i];
    int Btot = in_sizes[0] / 36;
    int per_block = NW * SPW;
    int blocks = (Btot + per_block - 1) / per_block;
    cad_kernel<<<blocks, NW * 32>>>(
        p[0], p[1], p[2], p[3], p[4], p[5], p[6], p[7], p[8], p[9], p[10],
        p[11], p[12], p[13], p[14], p[15], p[16], p[17], p[18],
        (float*)d_out, Btot);
}

// round 12
// speedup vs baseline: 1.3754x; 1.0317x over previous
#include <cuda_runtime.h>

#define FULL 0xffffffffu
constexpr int NW = 8;     // warps per block
constexpr int SPW = 8;    // samples per warp
constexpr int PAIRS = SPW / 2;

// per-sample-slot activation offsets (floats); ANF overlays AV (AV dead after adjacency)
constexpr int FSP = 0;    // factors, 6 rows stride 8 (48)
constexpr int AU  = 48;   // u / h2, 6 rows stride 36 (224)
constexpr int AV  = 272;  // v (224); ANF = h1/s1 overlays here (192)
constexpr int ANF = 272;
constexpr int ADJ = 496;  // adjacency rows stride 8 (48)
constexpr int ASP = 544;  // structured / pred rows stride 8 (48)
constexpr int ACT = 592;

__device__ __forceinline__ float sigm(float x) { return 1.0f / (1.0f + __expf(-x)); }

// 16-lane reduction (lanes >= 16 must hold 0)
__device__ __forceinline__ float wsum16(float t) {
#pragma unroll
    for (int o = 8; o; o >>= 1) t += __shfl_xor_sync(FULL, t, o);
    return t;
}

#define FMA4V(acc, vec, wv)                        \
    acc = fmaf((vec).x, (wv).x, acc);              \
    acc = fmaf((vec).y, (wv).y, acc);              \
    acc = fmaf((vec).z, (wv).z, acc);              \
    acc = fmaf((vec).w, (wv).w, acc);

#define LD4(arr, dst, off)                                        \
    { float4 _a = *(const float4*)&(arr)[off];                    \
      (dst)[0] = _a.x; (dst)[1] = _a.y; (dst)[2] = _a.z; (dst)[3] = _a.w; }

#define DOT6S(acc, r4, r2, wc)                     \
    acc = fmaf((r4).x, (wc)[0], acc);              \
    acc = fmaf((r4).y, (wc)[1], acc);              \
    acc = fmaf((r4).z, (wc)[2], acc);              \
    acc = fmaf((r4).w, (wc)[3], acc);              \
    acc = fmaf((r2).x, (wc)[4], acc);              \
    acc = fmaf((r2).y, (wc)[5], acc);

#define DOT6(acc, r4, r2, q4, q2)                  \
    acc = fmaf((r4).x, (q4).x, acc);               \
    acc = fmaf((r4).y, (q4).y, acc);               \
    acc = fmaf((r4).z, (q4).z, acc);               \
    acc = fmaf((r4).w, (q4).w, acc);               \
    acc = fmaf((r2).x, (q2).x, acc);               \
    acc = fmaf((r2).y, (q2).y, acc);

__global__ __launch_bounds__(NW * 32, 4) void cad_kernel(
    const float* __restrict__ factors,
    const float* __restrict__ Wn,  const float* __restrict__ bn,
    const float* __restrict__ We1, const float* __restrict__ be1,
    const float* __restrict__ We2, const float* __restrict__ be2,
    const float* __restrict__ Wd1, const float* __restrict__ bd1,
    const float* __restrict__ Wd2, const float* __restrict__ bd2,
    const float* __restrict__ Wd3, const float* __restrict__ bd3,
    const float* __restrict__ Ws1, const float* __restrict__ bs1,
    const float* __restrict__ Ws2, const float* __restrict__ bs2,
    const float* __restrict__ Ws3, const float* __restrict__ bs3,
    float* __restrict__ out, int Btot)
{
    __shared__ __align__(16) float WuS[192], WvS[192];
    __shared__ __align__(16) float wd1S[192];
    __shared__ __align__(16) float buS[32], bvS[32];
    __shared__ __align__(16) float wd2T[32 * 36];
    __shared__ __align__(16) float wd3F[6 * 36];
    __shared__ __align__(16) float ws1T[32 * 20];
    __shared__ __align__(16) float ws2T[16 * 36];
    __shared__ __align__(16) float we2S[32];
    __shared__ float bd1S[32], bd2S[32], bs1S[32];
    __shared__ float bs2S[16], ws3S[16], bd3S[8], scal[2];
    __shared__ __align__(16) float act[NW][2][ACT];

    const int tid = threadIdx.x;

    // ---- composed edge weights: Wu = Wn@We1[:32], Wv = Wn@We1[32:] ----
    if (tid < 192) {
        int f = tid >> 5, h = tid & 31;
        float au = 0.0f, av = 0.0f;
#pragma unroll 4
        for (int k = 0; k < 32; k++) {
            float wn = Wn[f * 32 + k];
            au = fmaf(wn, We1[k * 32 + h], au);
            av = fmaf(wn, We1[(32 + k) * 32 + h], av);
        }
        WuS[f * 32 + h] = au;
        WvS[f * 32 + h] = av;
        wd1S[f * 32 + h] = Wd1[f * 32 + h];
    }
    if (tid < 32) {
        float bu = be1[tid], bv = 0.0f;
#pragma unroll 4
        for (int k = 0; k < 32; k++) {
            float b = bn[k];
            bu = fmaf(b, We1[k * 32 + tid], bu);
            bv = fmaf(b, We1[(32 + k) * 32 + tid], bv);
        }
        buS[tid] = bu; bvS[tid] = bv;
    }
    for (int idx = tid; idx < 1024; idx += NW * 32) {
        int k = idx >> 5, l = idx & 31;
        wd2T[l * 36 + k] = Wd2[idx];
    }
    for (int idx = tid; idx < 576; idx += NW * 32) {
        int k = idx >> 5, l = idx & 31;
        ws1T[l * 20 + k] = Ws1[idx];
    }
    for (int idx = tid; idx < 512; idx += NW * 32) {
        int k = idx >> 4, m = idx & 15;
        ws2T[m * 36 + k] = Ws2[idx];
    }
    for (int idx = tid; idx < 192; idx += NW * 32) {
        int k3 = idx / 6, f3 = idx - k3 * 6;
        wd3F[f3 * 36 + k3] = Wd3[idx];
    }
    if (tid < 32) {
        we2S[tid] = We2[tid];
        bd1S[tid] = bd1[tid]; bd2S[tid] = bd2[tid]; bs1S[tid] = bs1[tid];
    }
    if (tid < 16) { bs2S[tid] = bs2[tid]; ws3S[tid] = Ws3[tid]; }
    if (tid < 6)  { bd3S[tid] = bd3[tid]; }
    if (tid == 0) { scal[0] = be2[0]; scal[1] = bs3[0]; }
    __syncthreads();

    const int lane = tid & 31;
    const int w = tid >> 5;

    const int i1 = lane / 6, j1 = lane - i1 * 6;   // element e = lane
    const int j2 = (lane < 4) ? lane + 2 : 2;      // element 32+lane -> (5, j2)

#pragma unroll 1
    for (int it = 0; it < PAIRS; it++) {
        const int b0 = ((blockIdx.x * NW + w) * SPW) + 2 * it;
        if (b0 < Btot) {
            const bool v1 = (b0 + 1) < Btot;

            // ---- stage factors ----
#pragma unroll
            for (int p = 0; p < 2; p++) {
                float* A = act[w][p];
                const float* fb = factors + (size_t)(p ? (v1 ? b0 + 1 : b0) : b0) * 36;
                A[FSP + i1 * 8 + j1] = fb[lane];
                if (lane < 4) A[FSP + 40 + j2] = fb[32 + lane];
            }
            __syncwarp();

            // ---- u,v via composed weights (weights loaded once per pair) ----
            {
                float wuC[6], wvC[6];
#pragma unroll
                for (int f = 0; f < 6; f++) {
                    wuC[f] = WuS[f * 32 + lane];
                    wvC[f] = WvS[f * 32 + lane];
                }
                float bul = buS[lane], bvl = bvS[lane];
#pragma unroll
                for (int p = 0; p < 2; p++) {
                    float* A = act[w][p];
#pragma unroll
                    for (int i = 0; i < 6; i++) {
                        float4 f4 = *(const float4*)&A[FSP + i * 8];
                        float2 f2 = *(const float2*)&A[FSP + i * 8 + 4];
                        float ui = bul, vi = bvl;
                        DOT6S(ui, f4, f2, wuC);
                        DOT6S(vi, f4, f2, wvC);
                        A[AU + i * 36 + lane] = ui;
                        A[AV + i * 36 + lane] = vi;
                    }
                }
            }
            __syncwarp();

            // ---- adjacency (lane = edge); we2 read once per t, both samples ----
            {
                float acc1[2] = {0.0f, 0.0f}, acc2[2] = {0.0f, 0.0f};
#pragma unroll
                for (int t = 0; t < 8; t++) {
                    float4 w2 = *(const float4*)&we2S[4 * t];
#pragma unroll
                    for (int p = 0; p < 2; p++) {
                        float* A = act[w][p];
                        float4 a1 = *(const float4*)&A[AU + i1 * 36 + 4 * t];
                        float4 b1 = *(const float4*)&A[AV + j1 * 36 + 4 * t];
                        acc1[p] = fmaf(fmaxf(a1.x + b1.x, 0.0f), w2.x, acc1[p]);
                        acc1[p] = fmaf(fmaxf(a1.y + b1.y, 0.0f), w2.y, acc1[p]);
                        acc1[p] = fmaf(fmaxf(a1.z + b1.z, 0.0f), w2.z, acc1[p]);
                        acc1[p] = fmaf(fmaxf(a1.w + b1.w, 0.0f), w2.w, acc1[p]);
                        float4 a2 = *(const float4*)&A[AU + 5 * 36 + 4 * t];
                        float4 b2 = *(const float4*)&A[AV + j2 * 36 + 4 * t];
                        acc2[p] = fmaf(fmaxf(a2.x + b2.x, 0.0f), w2.x, acc2[p]);
                        acc2[p] = fmaf(fmaxf(a2.y + b2.y, 0.0f), w2.y, acc2[p]);
                        acc2[p] = fmaf(fmaxf(a2.z + b2.z, 0.0f), w2.z, acc2[p]);
                        acc2[p] = fmaf(fmaxf(a2.w + b2.w, 0.0f), w2.w, acc2[p]);
                    }
                }
                float be2v = scal[0];
#pragma unroll
                for (int p = 0; p < 2; p++) {
                    float* A = act[w][p];
                    float a1v = (i1 == j1) ? 0.0f : sigm(acc1[p] + be2v);
                    float a2v = (lane == 3) ? 0.0f : sigm(acc2[p] + be2v);
                    A[ADJ + i1 * 8 + j1] = a1v;
                    if (lane < 4) A[ADJ + 40 + j2] = a2v;
                    if (p == 0 || v1) {
                        float* oa = out + (size_t)(b0 + p) * 36;
                        oa[lane] = a1v;
                        if (lane < 4) oa[32 + lane] = a2v;
                    }
                }
            }
            __syncwarp();

            // ---- structured (lane = (n=i1, i=j1)) ----
#pragma unroll
            for (int p = 0; p < 2; p++) {
                float* A = act[w][p];
                float4 ra4 = *(const float4*)&A[ADJ + j1 * 8];
                float2 ra2 = *(const float2*)&A[ADJ + j1 * 8 + 4];
                float4 rf4 = *(const float4*)&A[FSP + i1 * 8];
                float2 rf2 = *(const float2*)&A[FSP + i1 * 8 + 4];
                float sv = 0.0f;
                DOT6(sv, ra4, ra2, rf4, rf2);
                A[ASP + i1 * 8 + j1] = sv;
                if (lane < 4) {
                    float4 qa4 = *(const float4*)&A[ADJ + j2 * 8];
                    float2 qa2 = *(const float2*)&A[ADJ + j2 * 8 + 4];
                    float4 qf4 = *(const float4*)&A[FSP + 40];
                    float2 qf2 = *(const float2*)&A[FSP + 44];
                    float sv2 = 0.0f;
                    DOT6(sv2, qa4, qa2, qf4, qf2);
                    A[ASP + 40 + j2] = sv2;
                }
            }
            __syncwarp();

            // ---- h1 (lane = hidden); wd1 loaded once per pair ----
            {
                float wd1c[6];
#pragma unroll
                for (int f = 0; f < 6; f++) wd1c[f] = wd1S[f * 32 + lane];
                float bd1l = bd1S[lane];
#pragma unroll
                for (int p = 0; p < 2; p++) {
                    float* A = act[w][p];
#pragma unroll
                    for (int n = 0; n < 6; n++) {
                        float4 s4 = *(const float4*)&A[ASP + n * 8];
                        float2 s2 = *(const float2*)&A[ASP + n * 8 + 4];
                        float acc = bd1l;
                        DOT6S(acc, s4, s2, wd1c);
                        A[ANF + n * 32 + lane] = fmaxf(acc, 0.0f);
                    }
                }
            }
            __syncwarp();

            // ---- h2 interchanged; wd2 quad read once per t, both samples ----
            {
                float acc[2][6];
                float bd2l = bd2S[lane];
#pragma unroll
                for (int p = 0; p < 2; p++)
#pragma unroll
                    for (int n = 0; n < 6; n++) acc[p][n] = bd2l;
#pragma unroll
                for (int t = 0; t < 8; t++) {
                    float4 wv2 = *(const float4*)&wd2T[lane * 36 + 4 * t];
#pragma unroll
                    for (int p = 0; p < 2; p++) {
                        float* A = act[w][p];
#pragma unroll
                        for (int n = 0; n < 6; n++) {
                            float4 hv = *(const float4*)&A[ANF + n * 32 + 4 * t];
                            FMA4V(acc[p][n], hv, wv2);
                        }
                    }
                }
#pragma unroll
                for (int p = 0; p < 2; p++) {
                    float* A = act[w][p];
#pragma unroll
                    for (int n = 0; n < 6; n++)
                        A[AU + n * 36 + lane] = fmaxf(acc[p][n], 0.0f);
                }
            }
            __syncwarp();

            // ---- pred; wd3 quads read once per t ----
            {
                float pa[2] = {0.0f, 0.0f}, pb[2] = {0.0f, 0.0f};
#pragma unroll
                for (int t = 0; t < 8; t++) {
                    float4 w3a = *(const float4*)&wd3F[j1 * 36 + 4 * t];
                    float4 w3b = *(const float4*)&wd3F[j2 * 36 + 4 * t];
#pragma unroll
                    for (int p = 0; p < 2; p++) {
                        float* A = act[w][p];
                        float4 hv = *(const float4*)&A[AU + i1 * 36 + 4 * t];
                        FMA4V(pa[p], hv, w3a);
                        float4 h5 = *(const float4*)&A[AU + 5 * 36 + 4 * t];
                        FMA4V(pb[p], h5, w3b);
                    }
                }
                float bd3l = bd3S[j1], bd3l2 = bd3S[j2];
#pragma unroll
                for (int p = 0; p < 2; p++) {
                    float* A = act[w][p];
                    float p1 = pa[p] + bd3l;
                    float p2 = pb[p] + bd3l2;
                    A[ASP + i1 * 8 + j1] = p1;
                    if (lane < 4) A[ASP + 40 + j2] = p2;
                    if (p == 0 || v1) {
                        float* op = out + (size_t)Btot * 36 + (size_t)(b0 + p) * 36;
                        op[lane] = p1;
                        if (lane < 4) op[32 + lane] = p2;
                    }
                }
            }
            __syncwarp();

            // ---- scorer layer 1; ws1 loaded once per pair ----
            {
                float ws1c[18];
#pragma unroll
                for (int t = 0; t < 4; t++) LD4(ws1T, ws1c + 4 * t, lane * 20 + 4 * t);
                {
                    float2 a = *(const float2*)&ws1T[lane * 20 + 16];
                    ws1c[16] = a.x; ws1c[17] = a.y;
                }
                float bs1l = bs1S[lane];
#pragma unroll
                for (int p = 0; p < 2; p++) {
                    float* A = act[w][p];
#pragma unroll
                    for (int n = 0; n < 6; n++) {
                        float4 f4 = *(const float4*)&A[FSP + n * 8];
                        float2 f2 = *(const float2*)&A[FSP + n * 8 + 4];
                        float4 p4 = *(const float4*)&A[ASP + n * 8];
                        float2 p2 = *(const float2*)&A[ASP + n * 8 + 4];
                        float fk[6] = {f4.x, f4.y, f4.z, f4.w, f2.x, f2.y};
                        float pk[6] = {p4.x, p4.y, p4.z, p4.w, p2.x, p2.y};
                        float acc = bs1l;
#pragma unroll
                        for (int k = 0; k < 6; k++) {
                            acc = fmaf(fk[k], ws1c[k], acc);
                            acc = fmaf(pk[k], ws1c[6 + k], acc);
                            acc = fmaf(fabsf(fk[k] - pk[k]), ws1c[12 + k], acc);
                        }
                        A[ANF + n * 32 + lane] = fmaxf(acc, 0.0f);
                    }
                }
            }
            __syncwarp();

            // ---- scorer layers 2+3; ws2 quad once per t ----
            {
                float acc[2][6];
                float bs2l = bs2S[lane & 15];
#pragma unroll
                for (int p = 0; p < 2; p++)
#pragma unroll
                    for (int n = 0; n < 6; n++) acc[p][n] = bs2l;
#pragma unroll
                for (int t = 0; t < 8; t++) {
                    float4 wv2 = *(const float4*)&ws2T[(lane & 15) * 36 + 4 * t];
#pragma unroll
                    for (int p = 0; p < 2; p++) {
                        float* A = act[w][p];
#pragma unroll
                        for (int n = 0; n < 6; n++) {
                            float4 sv = *(const float4*)&A[ANF + n * 32 + 4 * t];
                            FMA4V(acc[p][n], sv, wv2);
                        }
                    }
                }
                float ws3l = (lane < 16) ? ws3S[lane] : 0.0f;
                float bs3v = scal[1];
#pragma unroll
                for (int p = 0; p < 2; p++) {
                    float ssum = 0.0f;
#pragma unroll
                    for (int n = 0; n < 6; n++) {
                        float tt = fmaxf(acc[p][n], 0.0f) * ws3l;  // lanes >= 16: 0
                        ssum += sigm(wsum16(tt) + bs3v);
                    }
                    if (lane == 0 && (p == 0 || v1))
                        out[(size_t)Btot * 72 + (b0 + p)] = ssum * (1.0f / 6.0f);
                }
            }
            __syncwarp();
        }
    }
}

extern "C" void kernel_launch(void* const* d_in, const int* in_sizes, int n_in,
                              void* d_out, int out_size) {
    const float* p[19];
    for (int i = 0; i < 19; i++) p[i] = (const float*)d_in[i];
    int Btot = in_sizes[0] / 36;
    int per_block = NW * SPW;
    int blocks = (Btot + per_block - 1) / per_block;
    cad_kernel<<<blocks, NW * 32>>>(
        p[0], p[1], p[2], p[3], p[4], p[5], p[6], p[7], p[8], p[9], p[10],
        p[11], p[12], p[13], p[14], p[15], p[16], p[17], p[18],
        (float*)d_out, Btot);
}